// round 14
// baseline (speedup 1.0000x reference)
#include <cuda_runtime.h>

// R13 = R12 + explicit W-stream software pipelining (register double-buffer,
// prefetch distance 1-2 k) in GEMMs 1/2/6/8 to cover ~240-cycle L2 latency
// (L1D is only ~24KB with 2x102KB smem resident, so W always hits L2).
// All layouts/phases identical to the passing R12 kernel.

typedef unsigned long long ull;
#define DEV __device__ __forceinline__

constexpr int ST = 68;   // padded transposed stride (16B-aligned)

DEV ull pack2(float x){ ull r; asm("mov.b64 %0, {%1, %1};" : "=l"(r) : "f"(x)); return r; }
DEV void fma2(ull& a, ull b, ull c){ asm("fma.rn.f32x2 %0, %1, %2, %0;" : "+l"(a) : "l"(b), "l"(c)); }
DEV float2 unpack2(ull v){ float2 f; asm("mov.b64 {%0, %1}, %2;" : "=f"(f.x), "=f"(f.y) : "l"(v)); return f; }
DEV float elem4(const float4& v,int k){ return k==0?v.x:k==1?v.y:k==2?v.z:v.w; }

// ---- M8 GEMM (4r x CPT c), A^T in smem stride ST, W in gmem ----
// k2-blocked with register double-buffered W prefetch (distance = 2 k).
template<int K, int CPT, int LDW>
DEV void gemmM_acc(const float* __restrict__ sAT, const float* __restrict__ W,
                   ull (&acc)[4][CPT/2], int R0, int wc0)
{
    constexpr int NP = CPT/2;
    ull wc[2][NP], wn[2][NP];
    #pragma unroll
    for (int t = 0; t < 2; t++)
        #pragma unroll
        for (int u = 0; u < CPT/4; u++) {
            ulonglong2 ww = *(const ulonglong2*)(W + t*LDW + wc0 + 32*u);
            wc[t][2*u] = ww.x; wc[t][2*u+1] = ww.y;
        }
    #pragma unroll 2
    for (int k2 = 0; k2 < K; k2 += 2) {
        if (k2 + 2 < K) {
            #pragma unroll
            for (int t = 0; t < 2; t++)
                #pragma unroll
                for (int u = 0; u < CPT/4; u++) {
                    ulonglong2 ww = *(const ulonglong2*)(W + (k2+2+t)*LDW + wc0 + 32*u);
                    wn[t][2*u] = ww.x; wn[t][2*u+1] = ww.y;
                }
        }
        #pragma unroll
        for (int t = 0; t < 2; t++) {
            float4 a = *(const float4*)(sAT + (k2+t)*ST + R0);
            ull b0 = pack2(a.x), b1 = pack2(a.y), b2 = pack2(a.z), b3 = pack2(a.w);
            #pragma unroll
            for (int j = 0; j < NP; j++) {
                fma2(acc[0][j], b0, wc[t][j]);
                fma2(acc[1][j], b1, wc[t][j]);
                fma2(acc[2][j], b2, wc[t][j]);
                fma2(acc[3][j], b3, wc[t][j]);
            }
        }
        #pragma unroll
        for (int t = 0; t < 2; t++)
            #pragma unroll
            for (int j = 0; j < NP; j++) wc[t][j] = wn[t][j];
    }
}

template<int CPT, bool RELU>
DEV void unpackM(const ull (&acc)[4][CPT/2], const float* __restrict__ bias,
                 int wc0, float (&v)[4][CPT])
{
    #pragma unroll
    for (int u = 0; u < CPT/4; u++)
        #pragma unroll
        for (int h = 0; h < 2; h++) {
            const int col = wc0 + 32*u + 2*h;
            const float bx = bias[col], by = bias[col+1];
            #pragma unroll
            for (int i = 0; i < 4; i++) {
                float2 f = unpack2(acc[i][2*u+h]);
                float x = f.x + bx, y = f.y + by;
                if (RELU) { x = fmaxf(x,0.f); y = fmaxf(y,0.f); }
                v[i][4*u+2*h] = x; v[i][4*u+2*h+1] = y;
            }
        }
}

template<int CPT>
DEV void storeM_T(const float (&v)[4][CPT], float* __restrict__ PT, int R0, int wc0)
{
    #pragma unroll
    for (int u = 0; u < CPT/4; u++)
        #pragma unroll
        for (int m = 0; m < 4; m++) {
            const int c = wc0 + 32*u + m;
            *(float4*)(PT + c*ST + R0) =
                make_float4(v[0][4*u+m], v[1][4*u+m], v[2][4*u+m], v[3][4*u+m]);
        }
}

// GEMM6 K-segment: 8x8 tile, distance-1 W prefetch (keeps regs under 128).
template<int K>
DEV void gemm6_seg(const float* __restrict__ sAT, const float* __restrict__ W,
                   ull (&acc)[8][4], int R6, int wc6)
{
    ull wc[4], wn[4];
    {
        ulonglong2 w0 = *(const ulonglong2*)(W + wc6);
        ulonglong2 w1 = *(const ulonglong2*)(W + wc6 + 32);
        wc[0] = w0.x; wc[1] = w0.y; wc[2] = w1.x; wc[3] = w1.y;
    }
    #pragma unroll 2
    for (int k = 0; k < K; k++) {
        if (k + 1 < K) {
            ulonglong2 w0 = *(const ulonglong2*)(W + (k+1)*256 + wc6);
            ulonglong2 w1 = *(const ulonglong2*)(W + (k+1)*256 + wc6 + 32);
            wn[0] = w0.x; wn[1] = w0.y; wn[2] = w1.x; wn[3] = w1.y;
        }
        float4 alo = *(const float4*)(sAT + k*ST + R6);
        float4 ahi = *(const float4*)(sAT + k*ST + R6 + 4);
        float av[8] = {alo.x,alo.y,alo.z,alo.w, ahi.x,ahi.y,ahi.z,ahi.w};
        #pragma unroll
        for (int i = 0; i < 8; i++) {
            ull bb = pack2(av[i]);
            #pragma unroll
            for (int j = 0; j < 4; j++) fma2(acc[i][j], bb, wc[j]);
        }
        wc[0] = wn[0]; wc[1] = wn[1]; wc[2] = wn[2]; wc[3] = wn[3];
    }
}

// ---- old row-major mapping (qkv, out-proj) ----
template<int K, int G, int LDA, int LDW>
DEV void gemmO_acc(const float* __restrict__ sA, const float* __restrict__ W,
                   ull (&acc)[4][G][2], int r0, int c0)
{
    #pragma unroll 2
    for (int k4 = 0; k4 < K; k4 += 4) {
        float4 a0 = *(const float4*)(sA + (r0+0)*LDA + k4);
        float4 a1 = *(const float4*)(sA + (r0+1)*LDA + k4);
        float4 a2 = *(const float4*)(sA + (r0+2)*LDA + k4);
        float4 a3 = *(const float4*)(sA + (r0+3)*LDA + k4);
        #pragma unroll
        for (int kk = 0; kk < 4; kk++) {
            ulonglong2 w[G];
            #pragma unroll
            for (int g = 0; g < G; g++)
                w[g] = *(const ulonglong2*)(W + (k4+kk)*LDW + c0 + 64*g);
            ull b0 = pack2(elem4(a0,kk)), b1 = pack2(elem4(a1,kk));
            ull b2 = pack2(elem4(a2,kk)), b3 = pack2(elem4(a3,kk));
            #pragma unroll
            for (int g = 0; g < G; g++) {
                fma2(acc[0][g][0],b0,w[g].x); fma2(acc[0][g][1],b0,w[g].y);
                fma2(acc[1][g][0],b1,w[g].x); fma2(acc[1][g][1],b1,w[g].y);
                fma2(acc[2][g][0],b2,w[g].x); fma2(acc[2][g][1],b2,w[g].y);
                fma2(acc[3][g][0],b3,w[g].x); fma2(acc[3][g][1],b3,w[g].y);
            }
        }
    }
}

template<int G, int LDC>
DEV void gemmO_store(const ull (&acc)[4][G][2], const float* __restrict__ bias,
                     float* __restrict__ C, int r0, int c0)
{
    #pragma unroll
    for (int g = 0; g < G; g++) {
        const int col = c0 + 64*g;
        float4 bv = *(const float4*)(bias + col);
        #pragma unroll
        for (int i = 0; i < 4; i++) {
            float2 lo = unpack2(acc[i][g][0]), hi = unpack2(acc[i][g][1]);
            *(float4*)(C + (r0+i)*LDC + col) =
                make_float4(lo.x+bv.x, lo.y+bv.y, hi.x+bv.z, hi.y+bv.w);
        }
    }
}

DEV void storePO_T(const ull (&acc)[4][1][2], const float* __restrict__ bias,
                   float* __restrict__ PT, int r0, int c0)
{
    #pragma unroll
    for (int jc = 0; jc < 4; jc++) {
        const float bv = bias[c0 + jc];
        float f[4];
        #pragma unroll
        for (int i = 0; i < 4; i++) {
            float2 p = unpack2(acc[i][0][jc >> 1]);
            f[i] = ((jc & 1) ? p.y : p.x) + bv;
        }
        *(float4*)(PT + (c0 + jc)*ST + r0) = make_float4(f[0], f[1], f[2], f[3]);
    }
}

DEV void attention(const float* __restrict__ sQKV, float* __restrict__ sCtx, int tid)
{
    const int warp = tid >> 5, lane = tid & 31;
    const int head = warp >> 1, qrow = ((warp & 1) << 5) + lane;
    const float* qp = sQKV + qrow*192 + head*16;
    float q[16];
    #pragma unroll
    for (int d = 0; d < 16; d++) q[d] = qp[d] * 0.25f;
    float s[64];
    #pragma unroll
    for (int j = 0; j < 64; j++) {
        const float4* kp = (const float4*)(sQKV + j*192 + 64 + head*16);
        float a = 0.f;
        #pragma unroll
        for (int t = 0; t < 4; t++) {
            float4 kv = kp[t];
            a += q[4*t]*kv.x + q[4*t+1]*kv.y + q[4*t+2]*kv.z + q[4*t+3]*kv.w;
        }
        s[j] = a;
    }
    float m = s[0];
    #pragma unroll
    for (int j = 1; j < 64; j++) m = fmaxf(m, s[j]);
    float sum = 0.f;
    #pragma unroll
    for (int j = 0; j < 64; j++) { s[j] = __expf(s[j] - m); sum += s[j]; }
    const float inv = 1.f / sum;
    float acc[16];
    #pragma unroll
    for (int d = 0; d < 16; d++) acc[d] = 0.f;
    #pragma unroll
    for (int j = 0; j < 64; j++) {
        const float4* vp = (const float4*)(sQKV + j*192 + 128 + head*16);
        float p = s[j];
        #pragma unroll
        for (int t = 0; t < 4; t++) {
            float4 vv = vp[t];
            acc[4*t] += p*vv.x; acc[4*t+1] += p*vv.y;
            acc[4*t+2] += p*vv.z; acc[4*t+3] += p*vv.w;
        }
    }
    float* cp = sCtx + qrow*ST + head*16;
    #pragma unroll
    for (int t = 0; t < 4; t++)
        *(float4*)(cp + 4*t) = make_float4(acc[4*t]*inv, acc[4*t+1]*inv,
                                           acc[4*t+2]*inv, acc[4*t+3]*inv);
}

__global__ void __launch_bounds__(256, 2)
comm_kernel(const float* __restrict__ obs,
            const float* __restrict__ enc_w1, const float* __restrict__ enc_b1,
            const float* __restrict__ enc_w2, const float* __restrict__ enc_b2,
            const float* __restrict__ in_proj_w, const float* __restrict__ in_proj_b,
            const float* __restrict__ out_w, const float* __restrict__ out_b,
            const float* __restrict__ int_w1, const float* __restrict__ int_b1,
            const float* __restrict__ ln_g, const float* __restrict__ ln_b,
            const float* __restrict__ int_w2, const float* __restrict__ int_b2,
            float* __restrict__ out_enriched, float* __restrict__ out_msgs)
{
    extern __shared__ float smem[];
    float* s_obsT = smem;            // 8704: obs^T; later LN scratch
    float* s_big  = smem + 8704;     // 17408: hT / qkv(12288) / zT(17408)
    float* s_aux  = s_big + 13056;   // 4352: msgs -> ctx -> aggT (stride ST)
    float2* part  = (float2*)s_obsT;          // [4 ch][64 rows]
    float2* stat  = ((float2*)s_obsT) + 256;  // [64] {mu, rs}

    const int b    = blockIdx.x;
    const int tid  = threadIdx.x;
    const int w    = tid >> 5, lane = tid & 31;
    const int quad = w & 3,  ch   = w >> 2;     // M8 mapping (4r x 8c)
    const int rl   = lane >> 3, cl = lane & 7;
    const int R0   = quad*16 + rl*4;
    const int r0   = (tid >> 4) << 2, c0 = (tid & 15) * 4;   // old mapping
    // GEMM6 mapping (8r x 8c): warp = 32 rows x 64 cols
    const int rh6  = w & 1, ch6 = w >> 1;
    const int R6   = rh6*32 + rl*8;
    const int wc6  = ch6*64 + cl*4;

    // ---- obs -> obs^T (stride ST)
    {
        const float* src = obs + (size_t)b * 8192 + (8*w) * 128;
        float rg[8][4];
        #pragma unroll
        for (int i = 0; i < 8; i++)
            #pragma unroll
            for (int t = 0; t < 4; t++)
                rg[i][t] = src[i*128 + 32*t + lane];
        #pragma unroll
        for (int t = 0; t < 4; t++) {
            const int k = 32*t + lane;
            *(float4*)(s_obsT + k*ST + 8*w)     =
                make_float4(rg[0][t], rg[1][t], rg[2][t], rg[3][t]);
            *(float4*)(s_obsT + k*ST + 8*w + 4) =
                make_float4(rg[4][t], rg[5][t], rg[6][t], rg[7][t]);
        }
    }
    __syncthreads();

    // 1) hT = relu(obs @ enc_w1 + b1)^T   K=128 NC=128
    {
        const int wc0 = ch*64 + cl*4;
        ull acc[4][4] = {};
        gemmM_acc<128,8,128>(s_obsT, enc_w1, acc, R0, wc0);
        float v[4][8];
        unpackM<8,true>(acc, enc_b1, wc0, v);
        storeM_T<8>(v, s_big, R0, wc0);
    }
    __syncthreads();

    // 2) msgs = h @ enc_w2 + b2   K=128 NC=64 -> s_aux (stride ST) + gmem
    {
        const int wc0 = ch*32 + cl*4;
        ull acc[4][2] = {};
        gemmM_acc<128,4,64>(s_big, enc_w2, acc, R0, wc0);
        float v[4][4];
        unpackM<4,false>(acc, enc_b2, wc0, v);
        float* gm = out_msgs + (size_t)b * 4096;
        #pragma unroll
        for (int i = 0; i < 4; i++) {
            float4 vv = make_float4(v[i][0], v[i][1], v[i][2], v[i][3]);
            *(float4*)(s_aux + (R0+i)*ST + wc0) = vv;
            *(float4*)(gm + (R0+i)*64 + wc0)    = vv;
        }
    }
    __syncthreads();

    // 3) qkv = msgs @ in_proj_w + b   K=64 NC=192 (old mapping) -> s_big
    {
        ull acc[4][3][2] = {};
        gemmO_acc<64,3,ST,192>(s_aux, in_proj_w, acc, r0, c0);
        gemmO_store<3,192>(acc, in_proj_b, s_big, r0, c0);
    }
    __syncthreads();

    // 4) attention -> ctx in s_aux (stride ST)
    attention(s_big, s_aux, tid);
    __syncthreads();

    // 5) aggT = (ctx @ out_w + b)^T -> s_aux
    {
        ull acc[4][1][2] = {};
        gemmO_acc<64,1,ST,64>(s_aux, out_w, acc, r0, c0);
        __syncthreads();
        storePO_T(acc, out_b, s_aux, r0, c0);
    }
    __syncthreads();

    // 6) zT = ([obs|agg] @ int_w1 + b)^T  K=192 NC=256 — single pass, 8x8 tile,
    //    distance-1 W prefetch per segment.
    float ps[8], pq[8];
    #pragma unroll
    for (int i = 0; i < 8; i++) { ps[i] = 0.f; pq[i] = 0.f; }
    {
        ull acc[8][4] = {};
        gemm6_seg<128>(s_obsT, int_w1 + wc6*0, acc, R6, wc6);       // obs part
        gemm6_seg<64>(s_aux,  int_w1 + 128*256, acc, R6, wc6);      // agg part
        __syncthreads();   // ALL warps done reading obsT/aggT -> stores safe

        #pragma unroll
        for (int u = 0; u < 2; u++) {
            const int cb = wc6 + 32*u;
            float4 bv = *(const float4*)(int_b1 + cb);
            float vu[8][4];
            #pragma unroll
            for (int i = 0; i < 8; i++) {
                float2 f0 = unpack2(acc[i][2*u]);
                float2 f1 = unpack2(acc[i][2*u+1]);
                vu[i][0] = f0.x + bv.x; vu[i][1] = f0.y + bv.y;
                vu[i][2] = f1.x + bv.z; vu[i][3] = f1.y + bv.w;
                #pragma unroll
                for (int m = 0; m < 4; m++) {
                    ps[i] += vu[i][m]; pq[i] += vu[i][m]*vu[i][m];
                }
            }
            #pragma unroll
            for (int m = 0; m < 4; m++) {
                float* p = s_big + (cb + m)*ST + R6;
                *(float4*)p     = make_float4(vu[0][m], vu[1][m], vu[2][m], vu[3][m]);
                *(float4*)(p+4) = make_float4(vu[4][m], vu[5][m], vu[6][m], vu[7][m]);
            }
        }
    }

    // LN row partials
    #pragma unroll
    for (int i = 0; i < 8; i++) {
        #pragma unroll
        for (int o = 1; o <= 4; o <<= 1) {
            ps[i] += __shfl_xor_sync(0xffffffffu, ps[i], o);
            pq[i] += __shfl_xor_sync(0xffffffffu, pq[i], o);
        }
    }
    if (cl == 0) {
        #pragma unroll
        for (int i = 0; i < 8; i++)
            part[ch6*64 + R6 + i] = make_float2(ps[i], pq[i]);
    }
    __syncthreads();

    if (tid < 64) {
        float s = 0.f, q = 0.f;
        #pragma unroll
        for (int c = 0; c < 4; c++) {
            float2 p = part[c*64 + tid];
            s += p.x; q += p.y;
        }
        const float mu = s * (1.f/256.f);
        const float rs = rsqrtf(q * (1.f/256.f) - mu*mu + 1e-5f);
        stat[tid] = make_float2(mu, rs);
    }
    __syncthreads();

    // LN apply + ReLU in place on zT
    {
        float2 st[8];
        #pragma unroll
        for (int i = 0; i < 8; i++) st[i] = stat[R6 + i];
        #pragma unroll
        for (int u = 0; u < 2; u++)
            #pragma unroll
            for (int m = 0; m < 4; m++) {
                const int c = wc6 + 32*u + m;
                const float gj = ln_g[c], bj = ln_b[c];
                float* zp = s_big + c*ST + R6;
                float4 lo = *(float4*)zp;
                float4 hi = *(float4*)(zp + 4);
                lo.x = fmaxf((lo.x - st[0].x)*st[0].y*gj + bj, 0.f);
                lo.y = fmaxf((lo.y - st[1].x)*st[1].y*gj + bj, 0.f);
                lo.z = fmaxf((lo.z - st[2].x)*st[2].y*gj + bj, 0.f);
                lo.w = fmaxf((lo.w - st[3].x)*st[3].y*gj + bj, 0.f);
                hi.x = fmaxf((hi.x - st[4].x)*st[4].y*gj + bj, 0.f);
                hi.y = fmaxf((hi.y - st[5].x)*st[5].y*gj + bj, 0.f);
                hi.z = fmaxf((hi.z - st[6].x)*st[6].y*gj + bj, 0.f);
                hi.w = fmaxf((hi.w - st[7].x)*st[7].y*gj + bj, 0.f);
                *(float4*)zp       = lo;
                *(float4*)(zp + 4) = hi;
            }
    }
    __syncthreads();

    // 8) enriched = z @ int_w2 + b -> gmem   K=256 NC=128
    {
        const int wc0 = ch*64 + cl*4;
        ull acc[4][4] = {};
        gemmM_acc<256,8,128>(s_big, int_w2, acc, R0, wc0);
        float v[4][8];
        unpackM<8,false>(acc, int_b2, wc0, v);
        float* dst = out_enriched + (size_t)b * 8192;
        #pragma unroll
        for (int i = 0; i < 4; i++)
            #pragma unroll
            for (int u = 0; u < 2; u++)
                *(float4*)(dst + (R0+i)*128 + wc0 + 32*u) =
                    make_float4(v[i][4*u], v[i][4*u+1], v[i][4*u+2], v[i][4*u+3]);
    }
}

extern "C" void kernel_launch(void* const* d_in, const int* in_sizes, int n_in,
                              void* d_out, int out_size)
{
    const float* obs       = (const float*)d_in[0];
    const float* enc_w1    = (const float*)d_in[1];
    const float* enc_b1    = (const float*)d_in[2];
    const float* enc_w2    = (const float*)d_in[3];
    const float* enc_b2    = (const float*)d_in[4];
    const float* in_proj_w = (const float*)d_in[5];
    const float* in_proj_b = (const float*)d_in[6];
    const float* out_w     = (const float*)d_in[7];
    const float* out_b     = (const float*)d_in[8];
    const float* int_w1    = (const float*)d_in[9];
    const float* int_b1    = (const float*)d_in[10];
    const float* ln_g      = (const float*)d_in[11];
    const float* ln_b      = (const float*)d_in[12];
    const float* int_w2    = (const float*)d_in[13];
    const float* int_b2    = (const float*)d_in[14];

    float* out_enriched = (float*)d_out;
    float* out_msgs     = (float*)d_out + (size_t)4096 * 64 * 128;

    const int smem_bytes = 26112 * sizeof(float);  // 104448 B -> 2 CTAs/SM
    cudaFuncSetAttribute(comm_kernel, cudaFuncAttributeMaxDynamicSharedMemorySize, smem_bytes);

    comm_kernel<<<4096, 256, smem_bytes>>>(
        obs, enc_w1, enc_b1, enc_w2, enc_b2,
        in_proj_w, in_proj_b, out_w, out_b,
        int_w1, int_b1, ln_g, ln_b, int_w2, int_b2,
        out_enriched, out_msgs);
}

// round 15
// speedup vs baseline: 1.1169x; 1.1169x over previous
#include <cuda_runtime.h>

// R14 = R12 (best passing, 1474us) with wider unroll windows ONLY:
//   gemmM_acc k-loop unroll 4 -> 8, GEMM6 segs unroll 2 -> 4, gemmO unroll 2 -> 4.
// Goal: deeper ptxas load hoisting (MLP ~8 -> ~12-16) to cover ~240cyc L2
// latency on the W stream WITHOUT the R13 register-copy MOV overhead.

typedef unsigned long long ull;
#define DEV __device__ __forceinline__

constexpr int ST = 68;   // padded transposed stride (16B-aligned)

DEV ull pack2(float x){ ull r; asm("mov.b64 %0, {%1, %1};" : "=l"(r) : "f"(x)); return r; }
DEV void fma2(ull& a, ull b, ull c){ asm("fma.rn.f32x2 %0, %1, %2, %0;" : "+l"(a) : "l"(b), "l"(c)); }
DEV float2 unpack2(ull v){ float2 f; asm("mov.b64 {%0, %1}, %2;" : "=f"(f.x), "=f"(f.y) : "l"(v)); return f; }
DEV float elem4(const float4& v,int k){ return k==0?v.x:k==1?v.y:k==2?v.z:v.w; }

// ---- M8 GEMM (4r x CPT c), A^T in smem stride ST, W in gmem ----
template<int K, int CPT, int LDW>
DEV void gemmM_acc(const float* __restrict__ sAT, const float* __restrict__ W,
                   ull (&acc)[4][CPT/2], int R0, int wc0)
{
    #pragma unroll 8
    for (int k = 0; k < K; k++) {
        float4 a = *(const float4*)(sAT + k*ST + R0);
        ull w2[CPT/2];
        #pragma unroll
        for (int u = 0; u < CPT/4; u++) {
            ulonglong2 ww = *(const ulonglong2*)(W + k*LDW + wc0 + 32*u);
            w2[2*u] = ww.x; w2[2*u+1] = ww.y;
        }
        ull b0 = pack2(a.x), b1 = pack2(a.y), b2 = pack2(a.z), b3 = pack2(a.w);
        #pragma unroll
        for (int j = 0; j < CPT/2; j++) {
            fma2(acc[0][j], b0, w2[j]);
            fma2(acc[1][j], b1, w2[j]);
            fma2(acc[2][j], b2, w2[j]);
            fma2(acc[3][j], b3, w2[j]);
        }
    }
}

template<int CPT, bool RELU>
DEV void unpackM(const ull (&acc)[4][CPT/2], const float* __restrict__ bias,
                 int wc0, float (&v)[4][CPT])
{
    #pragma unroll
    for (int u = 0; u < CPT/4; u++)
        #pragma unroll
        for (int h = 0; h < 2; h++) {
            const int col = wc0 + 32*u + 2*h;
            const float bx = bias[col], by = bias[col+1];
            #pragma unroll
            for (int i = 0; i < 4; i++) {
                float2 f = unpack2(acc[i][2*u+h]);
                float x = f.x + bx, y = f.y + by;
                if (RELU) { x = fmaxf(x,0.f); y = fmaxf(y,0.f); }
                v[i][4*u+2*h] = x; v[i][4*u+2*h+1] = y;
            }
        }
}

template<int CPT>
DEV void storeM_T(const float (&v)[4][CPT], float* __restrict__ PT, int R0, int wc0)
{
    #pragma unroll
    for (int u = 0; u < CPT/4; u++)
        #pragma unroll
        for (int m = 0; m < 4; m++) {
            const int c = wc0 + 32*u + m;
            *(float4*)(PT + c*ST + R0) =
                make_float4(v[0][4*u+m], v[1][4*u+m], v[2][4*u+m], v[3][4*u+m]);
        }
}

// ---- old row-major mapping (qkv, out-proj) ----
template<int K, int G, int LDA, int LDW>
DEV void gemmO_acc(const float* __restrict__ sA, const float* __restrict__ W,
                   ull (&acc)[4][G][2], int r0, int c0)
{
    #pragma unroll 4
    for (int k4 = 0; k4 < K; k4 += 4) {
        float4 a0 = *(const float4*)(sA + (r0+0)*LDA + k4);
        float4 a1 = *(const float4*)(sA + (r0+1)*LDA + k4);
        float4 a2 = *(const float4*)(sA + (r0+2)*LDA + k4);
        float4 a3 = *(const float4*)(sA + (r0+3)*LDA + k4);
        #pragma unroll
        for (int kk = 0; kk < 4; kk++) {
            ulonglong2 w[G];
            #pragma unroll
            for (int g = 0; g < G; g++)
                w[g] = *(const ulonglong2*)(W + (k4+kk)*LDW + c0 + 64*g);
            ull b0 = pack2(elem4(a0,kk)), b1 = pack2(elem4(a1,kk));
            ull b2 = pack2(elem4(a2,kk)), b3 = pack2(elem4(a3,kk));
            #pragma unroll
            for (int g = 0; g < G; g++) {
                fma2(acc[0][g][0],b0,w[g].x); fma2(acc[0][g][1],b0,w[g].y);
                fma2(acc[1][g][0],b1,w[g].x); fma2(acc[1][g][1],b1,w[g].y);
                fma2(acc[2][g][0],b2,w[g].x); fma2(acc[2][g][1],b2,w[g].y);
                fma2(acc[3][g][0],b3,w[g].x); fma2(acc[3][g][1],b3,w[g].y);
            }
        }
    }
}

template<int G, int LDC>
DEV void gemmO_store(const ull (&acc)[4][G][2], const float* __restrict__ bias,
                     float* __restrict__ C, int r0, int c0)
{
    #pragma unroll
    for (int g = 0; g < G; g++) {
        const int col = c0 + 64*g;
        float4 bv = *(const float4*)(bias + col);
        #pragma unroll
        for (int i = 0; i < 4; i++) {
            float2 lo = unpack2(acc[i][g][0]), hi = unpack2(acc[i][g][1]);
            *(float4*)(C + (r0+i)*LDC + col) =
                make_float4(lo.x+bv.x, lo.y+bv.y, hi.x+bv.z, hi.y+bv.w);
        }
    }
}

DEV void storePO_T(const ull (&acc)[4][1][2], const float* __restrict__ bias,
                   float* __restrict__ PT, int r0, int c0)
{
    #pragma unroll
    for (int jc = 0; jc < 4; jc++) {
        const float bv = bias[c0 + jc];
        float f[4];
        #pragma unroll
        for (int i = 0; i < 4; i++) {
            float2 p = unpack2(acc[i][0][jc >> 1]);
            f[i] = ((jc & 1) ? p.y : p.x) + bv;
        }
        *(float4*)(PT + (c0 + jc)*ST + r0) = make_float4(f[0], f[1], f[2], f[3]);
    }
}

DEV void attention(const float* __restrict__ sQKV, float* __restrict__ sCtx, int tid)
{
    const int warp = tid >> 5, lane = tid & 31;
    const int head = warp >> 1, qrow = ((warp & 1) << 5) + lane;
    const float* qp = sQKV + qrow*192 + head*16;
    float q[16];
    #pragma unroll
    for (int d = 0; d < 16; d++) q[d] = qp[d] * 0.25f;
    float s[64];
    #pragma unroll
    for (int j = 0; j < 64; j++) {
        const float4* kp = (const float4*)(sQKV + j*192 + 64 + head*16);
        float a = 0.f;
        #pragma unroll
        for (int t = 0; t < 4; t++) {
            float4 kv = kp[t];
            a += q[4*t]*kv.x + q[4*t+1]*kv.y + q[4*t+2]*kv.z + q[4*t+3]*kv.w;
        }
        s[j] = a;
    }
    float m = s[0];
    #pragma unroll
    for (int j = 1; j < 64; j++) m = fmaxf(m, s[j]);
    float sum = 0.f;
    #pragma unroll
    for (int j = 0; j < 64; j++) { s[j] = __expf(s[j] - m); sum += s[j]; }
    const float inv = 1.f / sum;
    float acc[16];
    #pragma unroll
    for (int d = 0; d < 16; d++) acc[d] = 0.f;
    #pragma unroll
    for (int j = 0; j < 64; j++) {
        const float4* vp = (const float4*)(sQKV + j*192 + 128 + head*16);
        float p = s[j];
        #pragma unroll
        for (int t = 0; t < 4; t++) {
            float4 vv = vp[t];
            acc[4*t] += p*vv.x; acc[4*t+1] += p*vv.y;
            acc[4*t+2] += p*vv.z; acc[4*t+3] += p*vv.w;
        }
    }
    float* cp = sCtx + qrow*ST + head*16;
    #pragma unroll
    for (int t = 0; t < 4; t++)
        *(float4*)(cp + 4*t) = make_float4(acc[4*t]*inv, acc[4*t+1]*inv,
                                           acc[4*t+2]*inv, acc[4*t+3]*inv);
}

__global__ void __launch_bounds__(256, 2)
comm_kernel(const float* __restrict__ obs,
            const float* __restrict__ enc_w1, const float* __restrict__ enc_b1,
            const float* __restrict__ enc_w2, const float* __restrict__ enc_b2,
            const float* __restrict__ in_proj_w, const float* __restrict__ in_proj_b,
            const float* __restrict__ out_w, const float* __restrict__ out_b,
            const float* __restrict__ int_w1, const float* __restrict__ int_b1,
            const float* __restrict__ ln_g, const float* __restrict__ ln_b,
            const float* __restrict__ int_w2, const float* __restrict__ int_b2,
            float* __restrict__ out_enriched, float* __restrict__ out_msgs)
{
    extern __shared__ float smem[];
    float* s_obsT = smem;            // 8704: obs^T; later LN scratch
    float* s_big  = smem + 8704;     // 17408: hT / qkv(12288) / zT(17408)
    float* s_aux  = s_big + 13056;   // 4352: msgs -> ctx -> aggT (stride ST)
    float2* part  = (float2*)s_obsT;          // [4 ch][64 rows]
    float2* stat  = ((float2*)s_obsT) + 256;  // [64] {mu, rs}

    const int b    = blockIdx.x;
    const int tid  = threadIdx.x;
    const int w    = tid >> 5, lane = tid & 31;
    const int quad = w & 3,  ch   = w >> 2;     // M8 mapping (4r x 8c)
    const int rl   = lane >> 3, cl = lane & 7;
    const int R0   = quad*16 + rl*4;
    const int r0   = (tid >> 4) << 2, c0 = (tid & 15) * 4;   // old mapping
    // GEMM6 mapping (8r x 8c): warp = 32 rows x 64 cols
    const int rh6  = w & 1, ch6 = w >> 1;
    const int R6   = rh6*32 + rl*8;
    const int wc6  = ch6*64 + cl*4;

    // ---- obs -> obs^T (stride ST)
    {
        const float* src = obs + (size_t)b * 8192 + (8*w) * 128;
        float rg[8][4];
        #pragma unroll
        for (int i = 0; i < 8; i++)
            #pragma unroll
            for (int t = 0; t < 4; t++)
                rg[i][t] = src[i*128 + 32*t + lane];
        #pragma unroll
        for (int t = 0; t < 4; t++) {
            const int k = 32*t + lane;
            *(float4*)(s_obsT + k*ST + 8*w)     =
                make_float4(rg[0][t], rg[1][t], rg[2][t], rg[3][t]);
            *(float4*)(s_obsT + k*ST + 8*w + 4) =
                make_float4(rg[4][t], rg[5][t], rg[6][t], rg[7][t]);
        }
    }
    __syncthreads();

    // 1) hT = relu(obs @ enc_w1 + b1)^T   K=128 NC=128
    {
        const int wc0 = ch*64 + cl*4;
        ull acc[4][4] = {};
        gemmM_acc<128,8,128>(s_obsT, enc_w1, acc, R0, wc0);
        float v[4][8];
        unpackM<8,true>(acc, enc_b1, wc0, v);
        storeM_T<8>(v, s_big, R0, wc0);
    }
    __syncthreads();

    // 2) msgs = h @ enc_w2 + b2   K=128 NC=64 -> s_aux (stride ST) + gmem
    {
        const int wc0 = ch*32 + cl*4;
        ull acc[4][2] = {};
        gemmM_acc<128,4,64>(s_big, enc_w2, acc, R0, wc0);
        float v[4][4];
        unpackM<4,false>(acc, enc_b2, wc0, v);
        float* gm = out_msgs + (size_t)b * 4096;
        #pragma unroll
        for (int i = 0; i < 4; i++) {
            float4 vv = make_float4(v[i][0], v[i][1], v[i][2], v[i][3]);
            *(float4*)(s_aux + (R0+i)*ST + wc0) = vv;
            *(float4*)(gm + (R0+i)*64 + wc0)    = vv;
        }
    }
    __syncthreads();

    // 3) qkv = msgs @ in_proj_w + b   K=64 NC=192 (old mapping) -> s_big
    {
        ull acc[4][3][2] = {};
        gemmO_acc<64,3,ST,192>(s_aux, in_proj_w, acc, r0, c0);
        gemmO_store<3,192>(acc, in_proj_b, s_big, r0, c0);
    }
    __syncthreads();

    // 4) attention -> ctx in s_aux (stride ST)
    attention(s_big, s_aux, tid);
    __syncthreads();

    // 5) aggT = (ctx @ out_w + b)^T -> s_aux
    {
        ull acc[4][1][2] = {};
        gemmO_acc<64,1,ST,64>(s_aux, out_w, acc, r0, c0);
        __syncthreads();
        storePO_T(acc, out_b, s_aux, r0, c0);
    }
    __syncthreads();

    // 6) zT = ([obs|agg] @ int_w1 + b)^T  K=192 NC=256 — single pass, 8x8 tile.
    float ps[8], pq[8];
    #pragma unroll
    for (int i = 0; i < 8; i++) { ps[i] = 0.f; pq[i] = 0.f; }
    {
        ull acc[8][4] = {};
        // K segment 1: obs (K=128)
        #pragma unroll 4
        for (int k = 0; k < 128; k++) {
            float4 alo = *(const float4*)(s_obsT + k*ST + R6);
            float4 ahi = *(const float4*)(s_obsT + k*ST + R6 + 4);
            ulonglong2 w0 = *(const ulonglong2*)(int_w1 + k*256 + wc6);
            ulonglong2 w1 = *(const ulonglong2*)(int_w1 + k*256 + wc6 + 32);
            ull w2[4] = {w0.x, w0.y, w1.x, w1.y};
            float av[8] = {alo.x,alo.y,alo.z,alo.w, ahi.x,ahi.y,ahi.z,ahi.w};
            #pragma unroll
            for (int i = 0; i < 8; i++) {
                ull bb = pack2(av[i]);
                #pragma unroll
                for (int j = 0; j < 4; j++) fma2(acc[i][j], bb, w2[j]);
            }
        }
        // K segment 2: agg (K=64)
        #pragma unroll 4
        for (int k = 0; k < 64; k++) {
            float4 alo = *(const float4*)(s_aux + k*ST + R6);
            float4 ahi = *(const float4*)(s_aux + k*ST + R6 + 4);
            const float* Wk = int_w1 + (128 + k)*256;
            ulonglong2 w0 = *(const ulonglong2*)(Wk + wc6);
            ulonglong2 w1 = *(const ulonglong2*)(Wk + wc6 + 32);
            ull w2[4] = {w0.x, w0.y, w1.x, w1.y};
            float av[8] = {alo.x,alo.y,alo.z,alo.w, ahi.x,ahi.y,ahi.z,ahi.w};
            #pragma unroll
            for (int i = 0; i < 8; i++) {
                ull bb = pack2(av[i]);
                #pragma unroll
                for (int j = 0; j < 4; j++) fma2(acc[i][j], bb, w2[j]);
            }
        }
        __syncthreads();   // ALL warps done reading obsT/aggT -> stores safe

        // streaming epilogue: per column-group u, unpack -> bias -> stats -> store
        #pragma unroll
        for (int u = 0; u < 2; u++) {
            const int cb = wc6 + 32*u;
            float4 bv = *(const float4*)(int_b1 + cb);
            float vu[8][4];
            #pragma unroll
            for (int i = 0; i < 8; i++) {
                float2 f0 = unpack2(acc[i][2*u]);
                float2 f1 = unpack2(acc[i][2*u+1]);
                vu[i][0] = f0.x + bv.x; vu[i][1] = f0.y + bv.y;
                vu[i][2] = f1.x + bv.z; vu[i][3] = f1.y + bv.w;
                #pragma unroll
                for (int m = 0; m < 4; m++) {
                    ps[i] += vu[i][m]; pq[i] += vu[i][m]*vu[i][m];
                }
            }
            #pragma unroll
            for (int m = 0; m < 4; m++) {
                float* p = s_big + (cb + m)*ST + R6;
                *(float4*)p     = make_float4(vu[0][m], vu[1][m], vu[2][m], vu[3][m]);
                *(float4*)(p+4) = make_float4(vu[4][m], vu[5][m], vu[6][m], vu[7][m]);
            }
        }
    }

    // LN row partials
    #pragma unroll
    for (int i = 0; i < 8; i++) {
        #pragma unroll
        for (int o = 1; o <= 4; o <<= 1) {
            ps[i] += __shfl_xor_sync(0xffffffffu, ps[i], o);
            pq[i] += __shfl_xor_sync(0xffffffffu, pq[i], o);
        }
    }
    if (cl == 0) {
        #pragma unroll
        for (int i = 0; i < 8; i++)
            part[ch6*64 + R6 + i] = make_float2(ps[i], pq[i]);
    }
    __syncthreads();

    if (tid < 64) {
        float s = 0.f, q = 0.f;
        #pragma unroll
        for (int c = 0; c < 4; c++) {
            float2 p = part[c*64 + tid];
            s += p.x; q += p.y;
        }
        const float mu = s * (1.f/256.f);
        const float rs = rsqrtf(q * (1.f/256.f) - mu*mu + 1e-5f);
        stat[tid] = make_float2(mu, rs);
    }
    __syncthreads();

    // LN apply + ReLU in place on zT
    {
        float2 st[8];
        #pragma unroll
        for (int i = 0; i < 8; i++) st[i] = stat[R6 + i];
        #pragma unroll
        for (int u = 0; u < 2; u++)
            #pragma unroll
            for (int m = 0; m < 4; m++) {
                const int c = wc6 + 32*u + m;
                const float gj = ln_g[c], bj = ln_b[c];
                float* zp = s_big + c*ST + R6;
                float4 lo = *(float4*)zp;
                float4 hi = *(float4*)(zp + 4);
                lo.x = fmaxf((lo.x - st[0].x)*st[0].y*gj + bj, 0.f);
                lo.y = fmaxf((lo.y - st[1].x)*st[1].y*gj + bj, 0.f);
                lo.z = fmaxf((lo.z - st[2].x)*st[2].y*gj + bj, 0.f);
                lo.w = fmaxf((lo.w - st[3].x)*st[3].y*gj + bj, 0.f);
                hi.x = fmaxf((hi.x - st[4].x)*st[4].y*gj + bj, 0.f);
                hi.y = fmaxf((hi.y - st[5].x)*st[5].y*gj + bj, 0.f);
                hi.z = fmaxf((hi.z - st[6].x)*st[6].y*gj + bj, 0.f);
                hi.w = fmaxf((hi.w - st[7].x)*st[7].y*gj + bj, 0.f);
                *(float4*)zp       = lo;
                *(float4*)(zp + 4) = hi;
            }
    }
    __syncthreads();

    // 8) enriched = z @ int_w2 + b -> gmem   K=256 NC=128
    {
        const int wc0 = ch*64 + cl*4;
        ull acc[4][4] = {};
        gemmM_acc<256,8,128>(s_big, int_w2, acc, R0, wc0);
        float v[4][8];
        unpackM<8,false>(acc, int_b2, wc0, v);
        float* dst = out_enriched + (size_t)b * 8192;
        #pragma unroll
        for (int i = 0; i < 4; i++)
            #pragma unroll
            for (int u = 0; u < 2; u++)
                *(float4*)(dst + (R0+i)*128 + wc0 + 32*u) =
                    make_float4(v[i][4*u], v[i][4*u+1], v[i][4*u+2], v[i][4*u+3]);
    }
}

extern "C" void kernel_launch(void* const* d_in, const int* in_sizes, int n_in,
                              void* d_out, int out_size)
{
    const float* obs       = (const float*)d_in[0];
    const float* enc_w1    = (const float*)d_in[1];
    const float* enc_b1    = (const float*)d_in[2];
    const float* enc_w2    = (const float*)d_in[3];
    const float* enc_b2    = (const float*)d_in[4];
    const float* in_proj_w = (const float*)d_in[5];
    const float* in_proj_b = (const float*)d_in[6];
    const float* out_w     = (const float*)d_in[7];
    const float* out_b     = (const float*)d_in[8];
    const float* int_w1    = (const float*)d_in[9];
    const float* int_b1    = (const float*)d_in[10];
    const float* ln_g      = (const float*)d_in[11];
    const float* ln_b      = (const float*)d_in[12];
    const float* int_w2    = (const float*)d_in[13];
    const float* int_b2    = (const float*)d_in[14];

    float* out_enriched = (float*)d_out;
    float* out_msgs     = (float*)d_out + (size_t)4096 * 64 * 128;

    const int smem_bytes = 26112 * sizeof(float);  // 104448 B -> 2 CTAs/SM
    cudaFuncSetAttribute(comm_kernel, cudaFuncAttributeMaxDynamicSharedMemorySize, smem_bytes);

    comm_kernel<<<4096, 256, smem_bytes>>>(
        obs, enc_w1, enc_b1, enc_w2, enc_b2,
        in_proj_w, in_proj_b, out_w, out_b,
        int_w1, int_b1, ln_g, ln_b, int_w2, int_b2,
        out_enriched, out_msgs);
}

// round 16
// speedup vs baseline: 1.1486x; 1.0284x over previous
#include <cuda_runtime.h>

// R15 = R14 (1399us) + GEMM1 & GEMM8 converted to 8x8-tile split-K2:
//   warp = (pos: 2 rowhalves x 2 colhalves) x (kh: 2 k-halves).
//   Mainloop per k: 2 LDS + 2 LDG for 32 FFMA2/thread (ratio 8 vs 5.3).
//   kh=1 warps write raw partials to dead smem; sync; kh=0 warps reduce+store.
// Everything else identical to R14.

typedef unsigned long long ull;
#define DEV __device__ __forceinline__

constexpr int ST = 68;   // padded transposed stride (16B-aligned)

DEV ull pack2(float x){ ull r; asm("mov.b64 %0, {%1, %1};" : "=l"(r) : "f"(x)); return r; }
DEV void fma2(ull& a, ull b, ull c){ asm("fma.rn.f32x2 %0, %1, %2, %0;" : "+l"(a) : "l"(b), "l"(c)); }
DEV float2 unpack2(ull v){ float2 f; asm("mov.b64 {%0, %1}, %2;" : "=f"(f.x), "=f"(f.y) : "l"(v)); return f; }
DEV float elem4(const float4& v,int k){ return k==0?v.x:k==1?v.y:k==2?v.z:v.w; }

// ---- M8 GEMM (4r x CPT c), A^T in smem stride ST, W in gmem ----
template<int K, int CPT, int LDW>
DEV void gemmM_acc(const float* __restrict__ sAT, const float* __restrict__ W,
                   ull (&acc)[4][CPT/2], int R0, int wc0)
{
    #pragma unroll 8
    for (int k = 0; k < K; k++) {
        float4 a = *(const float4*)(sAT + k*ST + R0);
        ull w2[CPT/2];
        #pragma unroll
        for (int u = 0; u < CPT/4; u++) {
            ulonglong2 ww = *(const ulonglong2*)(W + k*LDW + wc0 + 32*u);
            w2[2*u] = ww.x; w2[2*u+1] = ww.y;
        }
        ull b0 = pack2(a.x), b1 = pack2(a.y), b2 = pack2(a.z), b3 = pack2(a.w);
        #pragma unroll
        for (int j = 0; j < CPT/2; j++) {
            fma2(acc[0][j], b0, w2[j]);
            fma2(acc[1][j], b1, w2[j]);
            fma2(acc[2][j], b2, w2[j]);
            fma2(acc[3][j], b3, w2[j]);
        }
    }
}

template<int CPT, bool RELU>
DEV void unpackM(const ull (&acc)[4][CPT/2], const float* __restrict__ bias,
                 int wc0, float (&v)[4][CPT])
{
    #pragma unroll
    for (int u = 0; u < CPT/4; u++)
        #pragma unroll
        for (int h = 0; h < 2; h++) {
            const int col = wc0 + 32*u + 2*h;
            const float bx = bias[col], by = bias[col+1];
            #pragma unroll
            for (int i = 0; i < 4; i++) {
                float2 f = unpack2(acc[i][2*u+h]);
                float x = f.x + bx, y = f.y + by;
                if (RELU) { x = fmaxf(x,0.f); y = fmaxf(y,0.f); }
                v[i][4*u+2*h] = x; v[i][4*u+2*h+1] = y;
            }
        }
}

template<int CPT>
DEV void storeM_T(const float (&v)[4][CPT], float* __restrict__ PT, int R0, int wc0)
{
    #pragma unroll
    for (int u = 0; u < CPT/4; u++)
        #pragma unroll
        for (int m = 0; m < 4; m++) {
            const int c = wc0 + 32*u + m;
            *(float4*)(PT + c*ST + R0) =
                make_float4(v[0][4*u+m], v[1][4*u+m], v[2][4*u+m], v[3][4*u+m]);
        }
}

// ---- 8x8-tile split-K accumulate: rows R..R+7, cols C0+32u+{0..3} ----
template<int K2, int LDW>
DEV void gemmS_acc(const float* __restrict__ sAT, const float* __restrict__ W,
                   ull (&acc)[8][4], int R, int C0, int k0)
{
    #pragma unroll 4
    for (int k = 0; k < K2; k++) {
        const int kk = k0 + k;
        float4 alo = *(const float4*)(sAT + kk*ST + R);
        float4 ahi = *(const float4*)(sAT + kk*ST + R + 4);
        ulonglong2 w0 = *(const ulonglong2*)(W + kk*LDW + C0);
        ulonglong2 w1 = *(const ulonglong2*)(W + kk*LDW + C0 + 32);
        ull w2[4] = {w0.x, w0.y, w1.x, w1.y};
        float av[8] = {alo.x,alo.y,alo.z,alo.w, ahi.x,ahi.y,ahi.z,ahi.w};
        #pragma unroll
        for (int i = 0; i < 8; i++) {
            ull bb = pack2(av[i]);
            #pragma unroll
            for (int j = 0; j < 4; j++) fma2(acc[i][j], bb, w2[j]);
        }
    }
}

// unpack raw (no bias) 8x8 accumulators
DEV void unpackS(const ull (&acc)[8][4], float (&v)[8][8])
{
    #pragma unroll
    for (int i = 0; i < 8; i++)
        #pragma unroll
        for (int j = 0; j < 4; j++) {
            float2 f = unpack2(acc[i][j]);
            const int u = j >> 1, h = j & 1;
            v[i][4*u+2*h] = f.x; v[i][4*u+2*h+1] = f.y;
        }
}

// ---- old row-major mapping (qkv, out-proj) ----
template<int K, int G, int LDA, int LDW>
DEV void gemmO_acc(const float* __restrict__ sA, const float* __restrict__ W,
                   ull (&acc)[4][G][2], int r0, int c0)
{
    #pragma unroll 4
    for (int k4 = 0; k4 < K; k4 += 4) {
        float4 a0 = *(const float4*)(sA + (r0+0)*LDA + k4);
        float4 a1 = *(const float4*)(sA + (r0+1)*LDA + k4);
        float4 a2 = *(const float4*)(sA + (r0+2)*LDA + k4);
        float4 a3 = *(const float4*)(sA + (r0+3)*LDA + k4);
        #pragma unroll
        for (int kk = 0; kk < 4; kk++) {
            ulonglong2 w[G];
            #pragma unroll
            for (int g = 0; g < G; g++)
                w[g] = *(const ulonglong2*)(W + (k4+kk)*LDW + c0 + 64*g);
            ull b0 = pack2(elem4(a0,kk)), b1 = pack2(elem4(a1,kk));
            ull b2 = pack2(elem4(a2,kk)), b3 = pack2(elem4(a3,kk));
            #pragma unroll
            for (int g = 0; g < G; g++) {
                fma2(acc[0][g][0],b0,w[g].x); fma2(acc[0][g][1],b0,w[g].y);
                fma2(acc[1][g][0],b1,w[g].x); fma2(acc[1][g][1],b1,w[g].y);
                fma2(acc[2][g][0],b2,w[g].x); fma2(acc[2][g][1],b2,w[g].y);
                fma2(acc[3][g][0],b3,w[g].x); fma2(acc[3][g][1],b3,w[g].y);
            }
        }
    }
}

template<int G, int LDC>
DEV void gemmO_store(const ull (&acc)[4][G][2], const float* __restrict__ bias,
                     float* __restrict__ C, int r0, int c0)
{
    #pragma unroll
    for (int g = 0; g < G; g++) {
        const int col = c0 + 64*g;
        float4 bv = *(const float4*)(bias + col);
        #pragma unroll
        for (int i = 0; i < 4; i++) {
            float2 lo = unpack2(acc[i][g][0]), hi = unpack2(acc[i][g][1]);
            *(float4*)(C + (r0+i)*LDC + col) =
                make_float4(lo.x+bv.x, lo.y+bv.y, hi.x+bv.z, hi.y+bv.w);
        }
    }
}

DEV void storePO_T(const ull (&acc)[4][1][2], const float* __restrict__ bias,
                   float* __restrict__ PT, int r0, int c0)
{
    #pragma unroll
    for (int jc = 0; jc < 4; jc++) {
        const float bv = bias[c0 + jc];
        float f[4];
        #pragma unroll
        for (int i = 0; i < 4; i++) {
            float2 p = unpack2(acc[i][0][jc >> 1]);
            f[i] = ((jc & 1) ? p.y : p.x) + bv;
        }
        *(float4*)(PT + (c0 + jc)*ST + r0) = make_float4(f[0], f[1], f[2], f[3]);
    }
}

DEV void attention(const float* __restrict__ sQKV, float* __restrict__ sCtx, int tid)
{
    const int warp = tid >> 5, lane = tid & 31;
    const int head = warp >> 1, qrow = ((warp & 1) << 5) + lane;
    const float* qp = sQKV + qrow*192 + head*16;
    float q[16];
    #pragma unroll
    for (int d = 0; d < 16; d++) q[d] = qp[d] * 0.25f;
    float s[64];
    #pragma unroll
    for (int j = 0; j < 64; j++) {
        const float4* kp = (const float4*)(sQKV + j*192 + 64 + head*16);
        float a = 0.f;
        #pragma unroll
        for (int t = 0; t < 4; t++) {
            float4 kv = kp[t];
            a += q[4*t]*kv.x + q[4*t+1]*kv.y + q[4*t+2]*kv.z + q[4*t+3]*kv.w;
        }
        s[j] = a;
    }
    float m = s[0];
    #pragma unroll
    for (int j = 1; j < 64; j++) m = fmaxf(m, s[j]);
    float sum = 0.f;
    #pragma unroll
    for (int j = 0; j < 64; j++) { s[j] = __expf(s[j] - m); sum += s[j]; }
    const float inv = 1.f / sum;
    float acc[16];
    #pragma unroll
    for (int d = 0; d < 16; d++) acc[d] = 0.f;
    #pragma unroll
    for (int j = 0; j < 64; j++) {
        const float4* vp = (const float4*)(sQKV + j*192 + 128 + head*16);
        float p = s[j];
        #pragma unroll
        for (int t = 0; t < 4; t++) {
            float4 vv = vp[t];
            acc[4*t] += p*vv.x; acc[4*t+1] += p*vv.y;
            acc[4*t+2] += p*vv.z; acc[4*t+3] += p*vv.w;
        }
    }
    float* cp = sCtx + qrow*ST + head*16;
    #pragma unroll
    for (int t = 0; t < 4; t++)
        *(float4*)(cp + 4*t) = make_float4(acc[4*t]*inv, acc[4*t+1]*inv,
                                           acc[4*t+2]*inv, acc[4*t+3]*inv);
}

__global__ void __launch_bounds__(256, 2)
comm_kernel(const float* __restrict__ obs,
            const float* __restrict__ enc_w1, const float* __restrict__ enc_b1,
            const float* __restrict__ enc_w2, const float* __restrict__ enc_b2,
            const float* __restrict__ in_proj_w, const float* __restrict__ in_proj_b,
            const float* __restrict__ out_w, const float* __restrict__ out_b,
            const float* __restrict__ int_w1, const float* __restrict__ int_b1,
            const float* __restrict__ ln_g, const float* __restrict__ ln_b,
            const float* __restrict__ int_w2, const float* __restrict__ int_b2,
            float* __restrict__ out_enriched, float* __restrict__ out_msgs)
{
    extern __shared__ float smem[];
    float* s_obsT = smem;            // 8704: obs^T; later LN scratch + GEMM8 partials
    float* s_big  = smem + 8704;     // 17408: hT(+GEMM1 partials hi-half) / qkv / zT
    float* s_aux  = s_big + 13056;   // 4352: msgs -> ctx -> aggT (stride ST)
    float2* part  = (float2*)s_obsT;          // [4 ch][64 rows]
    float2* stat  = ((float2*)s_obsT) + 256;  // [64] {mu, rs}

    const int b    = blockIdx.x;
    const int tid  = threadIdx.x;
    const int w    = tid >> 5, lane = tid & 31;
    const int quad = w & 3,  ch   = w >> 2;     // M8 mapping (4r x 8c)
    const int rl   = lane >> 3, cl = lane & 7;
    const int R0   = quad*16 + rl*4;
    const int r0   = (tid >> 4) << 2, c0 = (tid & 15) * 4;   // old mapping
    // GEMM6 mapping (8r x 8c): warp = 32 rows x 64 cols
    const int rh6  = w & 1, ch6 = w >> 1;
    const int R6   = rh6*32 + rl*8;
    const int wc6  = ch6*64 + cl*4;
    // split-K 8x8 mapping (GEMM1 / GEMM8): pos = w&3, kh = w>>2
    const int pos  = w & 3, kh = w >> 2;
    const int R8   = (pos >> 1)*32 + rl*8;
    const int C8   = (pos & 1)*64 + cl*4;

    // ---- obs -> obs^T (stride ST)
    {
        const float* src = obs + (size_t)b * 8192 + (8*w) * 128;
        float rg[8][4];
        #pragma unroll
        for (int i = 0; i < 8; i++)
            #pragma unroll
            for (int t = 0; t < 4; t++)
                rg[i][t] = src[i*128 + 32*t + lane];
        #pragma unroll
        for (int t = 0; t < 4; t++) {
            const int k = 32*t + lane;
            *(float4*)(s_obsT + k*ST + 8*w)     =
                make_float4(rg[0][t], rg[1][t], rg[2][t], rg[3][t]);
            *(float4*)(s_obsT + k*ST + 8*w + 4) =
                make_float4(rg[4][t], rg[5][t], rg[6][t], rg[7][t]);
        }
    }
    __syncthreads();

    // 1) hT = relu(obs @ enc_w1 + b1)^T  K=128 NC=128 — 8x8 split-K2.
    //    Partials for kh=1 go to s_big[8704..16896) (dead zT upper half).
    {
        float* pbuf = s_big + 8704 + pos*2048;
        ull acc[8][4] = {};
        gemmS_acc<64,128>(s_obsT, enc_w1, acc, R8, C8, kh*64);
        float v[8][8];
        unpackS(acc, v);
        if (kh == 1) {
            #pragma unroll
            for (int i = 0; i < 8; i++)
                #pragma unroll
                for (int u = 0; u < 2; u++)
                    *(float4*)(pbuf + (rl*8+i)*64 + 32*u + cl*4) =
                        make_float4(v[i][4*u], v[i][4*u+1], v[i][4*u+2], v[i][4*u+3]);
        }
        __syncthreads();
        if (kh == 0) {
            float4 bv0 = *(const float4*)(enc_b1 + C8);
            float4 bv1 = *(const float4*)(enc_b1 + C8 + 32);
            #pragma unroll
            for (int i = 0; i < 8; i++) {
                float4 p0 = *(const float4*)(pbuf + (rl*8+i)*64 + cl*4);
                float4 p1 = *(const float4*)(pbuf + (rl*8+i)*64 + 32 + cl*4);
                v[i][0] = fmaxf(v[i][0]+p0.x+bv0.x, 0.f);
                v[i][1] = fmaxf(v[i][1]+p0.y+bv0.y, 0.f);
                v[i][2] = fmaxf(v[i][2]+p0.z+bv0.z, 0.f);
                v[i][3] = fmaxf(v[i][3]+p0.w+bv0.w, 0.f);
                v[i][4] = fmaxf(v[i][4]+p1.x+bv1.x, 0.f);
                v[i][5] = fmaxf(v[i][5]+p1.y+bv1.y, 0.f);
                v[i][6] = fmaxf(v[i][6]+p1.z+bv1.z, 0.f);
                v[i][7] = fmaxf(v[i][7]+p1.w+bv1.w, 0.f);
            }
            #pragma unroll
            for (int u = 0; u < 2; u++)
                #pragma unroll
                for (int m = 0; m < 4; m++) {
                    const int c = C8 + 32*u + m;
                    *(float4*)(s_big + c*ST + R8) =
                        make_float4(v[0][4*u+m], v[1][4*u+m], v[2][4*u+m], v[3][4*u+m]);
                    *(float4*)(s_big + c*ST + R8 + 4) =
                        make_float4(v[4][4*u+m], v[5][4*u+m], v[6][4*u+m], v[7][4*u+m]);
                }
        }
    }
    __syncthreads();

    // 2) msgs = h @ enc_w2 + b2   K=128 NC=64 -> s_aux (stride ST) + gmem
    {
        const int wc0 = ch*32 + cl*4;
        ull acc[4][2] = {};
        gemmM_acc<128,4,64>(s_big, enc_w2, acc, R0, wc0);
        float v[4][4];
        unpackM<4,false>(acc, enc_b2, wc0, v);
        float* gm = out_msgs + (size_t)b * 4096;
        #pragma unroll
        for (int i = 0; i < 4; i++) {
            float4 vv = make_float4(v[i][0], v[i][1], v[i][2], v[i][3]);
            *(float4*)(s_aux + (R0+i)*ST + wc0) = vv;
            *(float4*)(gm + (R0+i)*64 + wc0)    = vv;
        }
    }
    __syncthreads();

    // 3) qkv = msgs @ in_proj_w + b   K=64 NC=192 (old mapping) -> s_big
    {
        ull acc[4][3][2] = {};
        gemmO_acc<64,3,ST,192>(s_aux, in_proj_w, acc, r0, c0);
        gemmO_store<3,192>(acc, in_proj_b, s_big, r0, c0);
    }
    __syncthreads();

    // 4) attention -> ctx in s_aux (stride ST)
    attention(s_big, s_aux, tid);
    __syncthreads();

    // 5) aggT = (ctx @ out_w + b)^T -> s_aux
    {
        ull acc[4][1][2] = {};
        gemmO_acc<64,1,ST,64>(s_aux, out_w, acc, r0, c0);
        __syncthreads();
        storePO_T(acc, out_b, s_aux, r0, c0);
    }
    __syncthreads();

    // 6) zT = ([obs|agg] @ int_w1 + b)^T  K=192 NC=256 — single pass, 8x8 tile.
    float ps[8], pq[8];
    #pragma unroll
    for (int i = 0; i < 8; i++) { ps[i] = 0.f; pq[i] = 0.f; }
    {
        ull acc[8][4] = {};
        #pragma unroll 4
        for (int k = 0; k < 128; k++) {
            float4 alo = *(const float4*)(s_obsT + k*ST + R6);
            float4 ahi = *(const float4*)(s_obsT + k*ST + R6 + 4);
            ulonglong2 w0 = *(const ulonglong2*)(int_w1 + k*256 + wc6);
            ulonglong2 w1 = *(const ulonglong2*)(int_w1 + k*256 + wc6 + 32);
            ull w2[4] = {w0.x, w0.y, w1.x, w1.y};
            float av[8] = {alo.x,alo.y,alo.z,alo.w, ahi.x,ahi.y,ahi.z,ahi.w};
            #pragma unroll
            for (int i = 0; i < 8; i++) {
                ull bb = pack2(av[i]);
                #pragma unroll
                for (int j = 0; j < 4; j++) fma2(acc[i][j], bb, w2[j]);
            }
        }
        #pragma unroll 4
        for (int k = 0; k < 64; k++) {
            float4 alo = *(const float4*)(s_aux + k*ST + R6);
            float4 ahi = *(const float4*)(s_aux + k*ST + R6 + 4);
            const float* Wk = int_w1 + (128 + k)*256;
            ulonglong2 w0 = *(const ulonglong2*)(Wk + wc6);
            ulonglong2 w1 = *(const ulonglong2*)(Wk + wc6 + 32);
            ull w2[4] = {w0.x, w0.y, w1.x, w1.y};
            float av[8] = {alo.x,alo.y,alo.z,alo.w, ahi.x,ahi.y,ahi.z,ahi.w};
            #pragma unroll
            for (int i = 0; i < 8; i++) {
                ull bb = pack2(av[i]);
                #pragma unroll
                for (int j = 0; j < 4; j++) fma2(acc[i][j], bb, w2[j]);
            }
        }
        __syncthreads();   // ALL warps done reading obsT/aggT -> stores safe

        #pragma unroll
        for (int u = 0; u < 2; u++) {
            const int cb = wc6 + 32*u;
            float4 bv = *(const float4*)(int_b1 + cb);
            float vu[8][4];
            #pragma unroll
            for (int i = 0; i < 8; i++) {
                float2 f0 = unpack2(acc[i][2*u]);
                float2 f1 = unpack2(acc[i][2*u+1]);
                vu[i][0] = f0.x + bv.x; vu[i][1] = f0.y + bv.y;
                vu[i][2] = f1.x + bv.z; vu[i][3] = f1.y + bv.w;
                #pragma unroll
                for (int m = 0; m < 4; m++) {
                    ps[i] += vu[i][m]; pq[i] += vu[i][m]*vu[i][m];
                }
            }
            #pragma unroll
            for (int m = 0; m < 4; m++) {
                float* p = s_big + (cb + m)*ST + R6;
                *(float4*)p     = make_float4(vu[0][m], vu[1][m], vu[2][m], vu[3][m]);
                *(float4*)(p+4) = make_float4(vu[4][m], vu[5][m], vu[6][m], vu[7][m]);
            }
        }
    }

    // LN row partials
    #pragma unroll
    for (int i = 0; i < 8; i++) {
        #pragma unroll
        for (int o = 1; o <= 4; o <<= 1) {
            ps[i] += __shfl_xor_sync(0xffffffffu, ps[i], o);
            pq[i] += __shfl_xor_sync(0xffffffffu, pq[i], o);
        }
    }
    if (cl == 0) {
        #pragma unroll
        for (int i = 0; i < 8; i++)
            part[ch6*64 + R6 + i] = make_float2(ps[i], pq[i]);
    }
    __syncthreads();

    if (tid < 64) {
        float s = 0.f, q = 0.f;
        #pragma unroll
        for (int c = 0; c < 4; c++) {
            float2 p = part[c*64 + tid];
            s += p.x; q += p.y;
        }
        const float mu = s * (1.f/256.f);
        const float rs = rsqrtf(q * (1.f/256.f) - mu*mu + 1e-5f);
        stat[tid] = make_float2(mu, rs);
    }
    __syncthreads();

    // LN apply + ReLU in place on zT
    {
        float2 st[8];
        #pragma unroll
        for (int i = 0; i < 8; i++) st[i] = stat[R6 + i];
        #pragma unroll
        for (int u = 0; u < 2; u++)
            #pragma unroll
            for (int m = 0; m < 4; m++) {
                const int c = wc6 + 32*u + m;
                const float gj = ln_g[c], bj = ln_b[c];
                float* zp = s_big + c*ST + R6;
                float4 lo = *(float4*)zp;
                float4 hi = *(float4*)(zp + 4);
                lo.x = fmaxf((lo.x - st[0].x)*st[0].y*gj + bj, 0.f);
                lo.y = fmaxf((lo.y - st[1].x)*st[1].y*gj + bj, 0.f);
                lo.z = fmaxf((lo.z - st[2].x)*st[2].y*gj + bj, 0.f);
                lo.w = fmaxf((lo.w - st[3].x)*st[3].y*gj + bj, 0.f);
                hi.x = fmaxf((hi.x - st[4].x)*st[4].y*gj + bj, 0.f);
                hi.y = fmaxf((hi.y - st[5].x)*st[5].y*gj + bj, 0.f);
                hi.z = fmaxf((hi.z - st[6].x)*st[6].y*gj + bj, 0.f);
                hi.w = fmaxf((hi.w - st[7].x)*st[7].y*gj + bj, 0.f);
                *(float4*)zp       = lo;
                *(float4*)(zp + 4) = hi;
            }
    }
    __syncthreads();

    // 8) enriched = z @ int_w2 + b -> gmem  K=256 NC=128 — 8x8 split-K2.
    //    Partials for kh=1 go to dead obsT region.
    {
        float* pbuf = s_obsT + pos*2048;
        ull acc[8][4] = {};
        gemmS_acc<128,128>(s_big, int_w2, acc, R8, C8, kh*128);
        float v[8][8];
        unpackS(acc, v);
        if (kh == 1) {
            #pragma unroll
            for (int i = 0; i < 8; i++)
                #pragma unroll
                for (int u = 0; u < 2; u++)
                    *(float4*)(pbuf + (rl*8+i)*64 + 32*u + cl*4) =
                        make_float4(v[i][4*u], v[i][4*u+1], v[i][4*u+2], v[i][4*u+3]);
        }
        __syncthreads();
        if (kh == 0) {
            float4 bv0 = *(const float4*)(int_b2 + C8);
            float4 bv1 = *(const float4*)(int_b2 + C8 + 32);
            float* dst = out_enriched + (size_t)b * 8192;
            #pragma unroll
            for (int i = 0; i < 8; i++) {
                float4 p0 = *(const float4*)(pbuf + (rl*8+i)*64 + cl*4);
                float4 p1 = *(const float4*)(pbuf + (rl*8+i)*64 + 32 + cl*4);
                float4 o0 = make_float4(v[i][0]+p0.x+bv0.x, v[i][1]+p0.y+bv0.y,
                                        v[i][2]+p0.z+bv0.z, v[i][3]+p0.w+bv0.w);
                float4 o1 = make_float4(v[i][4]+p1.x+bv1.x, v[i][5]+p1.y+bv1.y,
                                        v[i][6]+p1.z+bv1.z, v[i][7]+p1.w+bv1.w);
                *(float4*)(dst + (R8+i)*128 + C8)      = o0;
                *(float4*)(dst + (R8+i)*128 + C8 + 32) = o1;
            }
        }
    }
}

extern "C" void kernel_launch(void* const* d_in, const int* in_sizes, int n_in,
                              void* d_out, int out_size)
{
    const float* obs       = (const float*)d_in[0];
    const float* enc_w1    = (const float*)d_in[1];
    const float* enc_b1    = (const float*)d_in[2];
    const float* enc_w2    = (const float*)d_in[3];
    const float* enc_b2    = (const float*)d_in[4];
    const float* in_proj_w = (const float*)d_in[5];
    const float* in_proj_b = (const float*)d_in[6];
    const float* out_w     = (const float*)d_in[7];
    const float* out_b     = (const float*)d_in[8];
    const float* int_w1    = (const float*)d_in[9];
    const float* int_b1    = (const float*)d_in[10];
    const float* ln_g      = (const float*)d_in[11];
    const float* ln_b      = (const float*)d_in[12];
    const float* int_w2    = (const float*)d_in[13];
    const float* int_b2    = (const float*)d_in[14];

    float* out_enriched = (float*)d_out;
    float* out_msgs     = (float*)d_out + (size_t)4096 * 64 * 128;

    const int smem_bytes = 26112 * sizeof(float);  // 104448 B -> 2 CTAs/SM
    cudaFuncSetAttribute(comm_kernel, cudaFuncAttributeMaxDynamicSharedMemorySize, smem_bytes);

    comm_kernel<<<4096, 256, smem_bytes>>>(
        obs, enc_w1, enc_b1, enc_w2, enc_b2,
        in_proj_w, in_proj_b, out_w, out_b,
        int_w1, int_b1, ln_g, ln_b, int_w2, int_b2,
        out_enriched, out_msgs);
}